// round 5
// baseline (speedup 1.0000x reference)
#include <cuda_runtime.h>
#include <cstdint>

// Problem constants (from reference): N=100000, C=128, E=3200000
#define MAXN 100000
#define CH 128
#define MAXE 3200000

// Scratch (device globals -- no allocation allowed)
__device__ float g_deg[MAXN];
__device__ float g_dinv[MAXN];
__device__ float g_h[(size_t)MAXN * CH];    // x @ Wc^T
__device__ float g_agg[(size_t)MAXN * CH];  // aggregated messages
__device__ float g_h2[(size_t)MAXN * CH];   // hidden after fc

// ---------------------------------------------------------------------------
// degree / normalization   (edge_index is int32 -- JAX default x64-disabled)
// ---------------------------------------------------------------------------
__global__ void k_deg_init(int n) {
    int i = blockIdx.x * blockDim.x + threadIdx.x;
    if (i < n) g_deg[i] = 1.0f;  // self-loop weight
}

__global__ void k_deg_accum(const int* __restrict__ dst,
                            const float* __restrict__ ew, int E) {
    int i = blockIdx.x * blockDim.x + threadIdx.x;
    if (i < E) {
        int d = dst[i];
        atomicAdd(&g_deg[d], ew[i]);
    }
}

__global__ void k_dinv(int n) {
    int i = blockIdx.x * blockDim.x + threadIdx.x;
    if (i < n) {
        float d = g_deg[i];
        g_dinv[i] = (d > 0.0f) ? rsqrtf(d) : 0.0f;
    }
}

// ---------------------------------------------------------------------------
// self-loop init: agg[i][:] = h[i][:] * dinv[i]^2
// ---------------------------------------------------------------------------
__global__ void k_selfloop(int n) {
    int idx = blockIdx.x * blockDim.x + threadIdx.x;  // one float4 per thread
    int total = n * (CH / 4);
    if (idx >= total) return;
    int row = idx >> 5;  // CH/4 = 32 float4 per row
    float di = g_dinv[row];
    float w = di * di;
    float4 v = ((const float4*)g_h)[idx];
    v.x *= w; v.y *= w; v.z *= w; v.w *= w;
    ((float4*)g_agg)[idx] = v;
}

// ---------------------------------------------------------------------------
// edge scatter: agg[dst] += h[src] * (dinv[src]*ew*dinv[dst])
// one warp per edge (grid-stride), vectorized red.global.add.v4.f32
// ---------------------------------------------------------------------------
__global__ void k_scatter(const int* __restrict__ src,
                          const int* __restrict__ dst,
                          const float* __restrict__ ew, int E) {
    int lane = threadIdx.x & 31;
    int w = (blockIdx.x * blockDim.x + threadIdx.x) >> 5;
    int nw = (gridDim.x * blockDim.x) >> 5;
    for (int e = w; e < E; e += nw) {
        int s = src[e];
        int d = dst[e];
        float nrm = g_dinv[s] * ew[e] * g_dinv[d];
        const float4* hs = (const float4*)(g_h + (size_t)s * CH);
        float4 v = hs[lane];
        v.x *= nrm; v.y *= nrm; v.z *= nrm; v.w *= nrm;
        float4* p = (float4*)(g_agg + (size_t)d * CH) + lane;
        asm volatile("red.global.add.v4.f32 [%0], {%1,%2,%3,%4};"
                     :: "l"(p), "f"(v.x), "f"(v.y), "f"(v.z), "f"(v.w)
                     : "memory");
    }
}

// ---------------------------------------------------------------------------
// SGEMM: C[m][n] = g( f(A[m][k]) * W[n][k] + bout[n] )
//   f(a) = RELU_IN ? relu(a + bin[k]) : a
//   g(c) = RELU_OUT ? relu(c) : c
// BM=128, BN=128 (full N), BK=32, 256 threads, 8x8 micro-tile.
// Transposed smem tiles [k][m]/[k][n] with stride 132 (LDS.128-friendly).
// ---------------------------------------------------------------------------
#define SSTR 132

template <bool RELU_IN, bool HAS_BOUT, bool RELU_OUT>
__global__ __launch_bounds__(256) void k_gemm(
    const float* __restrict__ A, const float* __restrict__ W,
    const float* __restrict__ bin, const float* __restrict__ bout,
    float* __restrict__ C, int M)
{
    __shared__ float As[32][SSTR];
    __shared__ float Ws[32][SSTR];

    int tid = threadIdx.x;
    int row0 = blockIdx.x * 128;
    int tx = tid & 15;
    int ty = tid >> 4;

    float acc[8][8];
#pragma unroll
    for (int i = 0; i < 8; i++)
#pragma unroll
        for (int j = 0; j < 8; j++) acc[i][j] = 0.0f;

    int lr = tid >> 3;          // 0..31 : row within group of 32
    int lk = (tid & 7) * 4;     // 0..28 : k offset (float4)

    for (int k0 = 0; k0 < CH; k0 += 32) {
        // ---- load A tile (transposed store) ----
#pragma unroll
        for (int i = 0; i < 4; i++) {
            int r = lr + 32 * i;
            int gr = row0 + r;
            float4 v = make_float4(0.f, 0.f, 0.f, 0.f);
            if (gr < M) v = *(const float4*)(A + (size_t)gr * CH + k0 + lk);
            if (RELU_IN) {
                v.x = fmaxf(v.x + bin[k0 + lk + 0], 0.f);
                v.y = fmaxf(v.y + bin[k0 + lk + 1], 0.f);
                v.z = fmaxf(v.z + bin[k0 + lk + 2], 0.f);
                v.w = fmaxf(v.w + bin[k0 + lk + 3], 0.f);
            }
            As[lk + 0][r] = v.x;
            As[lk + 1][r] = v.y;
            As[lk + 2][r] = v.z;
            As[lk + 3][r] = v.w;
        }
        // ---- load W tile (transposed store) ----
#pragma unroll
        for (int i = 0; i < 4; i++) {
            int nn = lr + 32 * i;
            float4 v = *(const float4*)(W + (size_t)nn * CH + k0 + lk);
            Ws[lk + 0][nn] = v.x;
            Ws[lk + 1][nn] = v.y;
            Ws[lk + 2][nn] = v.z;
            Ws[lk + 3][nn] = v.w;
        }
        __syncthreads();

#pragma unroll
        for (int k = 0; k < 32; k++) {
            float a[8], b[8];
            *(float4*)(a)     = *(const float4*)&As[k][ty * 4];
            *(float4*)(a + 4) = *(const float4*)&As[k][64 + ty * 4];
            *(float4*)(b)     = *(const float4*)&Ws[k][tx * 4];
            *(float4*)(b + 4) = *(const float4*)&Ws[k][64 + tx * 4];
#pragma unroll
            for (int i = 0; i < 8; i++)
#pragma unroll
                for (int j = 0; j < 8; j++)
                    acc[i][j] = fmaf(a[i], b[j], acc[i][j]);
        }
        __syncthreads();
    }

    // ---- epilogue ----
#pragma unroll
    for (int i = 0; i < 8; i++) {
        int r = (i < 4) ? (ty * 4 + i) : (64 + ty * 4 + (i - 4));
        int gr = row0 + r;
        if (gr >= M) continue;
#pragma unroll
        for (int jj = 0; jj < 2; jj++) {
            int nbase = (jj == 0) ? (tx * 4) : (64 + tx * 4);
            float4 o;
            o.x = acc[i][jj * 4 + 0];
            o.y = acc[i][jj * 4 + 1];
            o.z = acc[i][jj * 4 + 2];
            o.w = acc[i][jj * 4 + 3];
            if (HAS_BOUT) {
                o.x += bout[nbase + 0];
                o.y += bout[nbase + 1];
                o.z += bout[nbase + 2];
                o.w += bout[nbase + 3];
            }
            if (RELU_OUT) {
                o.x = fmaxf(o.x, 0.f);
                o.y = fmaxf(o.y, 0.f);
                o.z = fmaxf(o.z, 0.f);
                o.w = fmaxf(o.w, 0.f);
            }
            *(float4*)(C + (size_t)gr * CH + nbase) = o;
        }
    }
}

// ---------------------------------------------------------------------------
// launch
// ---------------------------------------------------------------------------
extern "C" void kernel_launch(void* const* d_in, const int* in_sizes, int n_in,
                              void* d_out, int out_size) {
    const float* x   = (const float*)d_in[0];
    const int*   ei  = (const int*)d_in[1];    // int32! (JAX x64 disabled)
    const float* ew  = (const float*)d_in[2];
    const float* Wc  = (const float*)d_in[3];
    const float* bc  = (const float*)d_in[4];
    const float* Wf  = (const float*)d_in[5];
    const float* bf  = (const float*)d_in[6];
    const float* Wf2 = (const float*)d_in[7];
    const float* bf2 = (const float*)d_in[8];
    float*       out = (float*)d_out;

    int n = in_sizes[0] / CH;
    int E = in_sizes[2];
    const int* src = ei;
    const int* dst = ei + E;

    float *p_h, *p_agg, *p_h2;
    cudaGetSymbolAddress((void**)&p_h, g_h);
    cudaGetSymbolAddress((void**)&p_agg, g_agg);
    cudaGetSymbolAddress((void**)&p_h2, g_h2);

    // 1. degree + dinv
    k_deg_init<<<(n + 255) / 256, 256>>>(n);
    k_deg_accum<<<(E + 255) / 256, 256>>>(dst, ew, E);
    k_dinv<<<(n + 255) / 256, 256>>>(n);

    // 2. h = x @ Wc^T
    int gb = (n + 127) / 128;
    k_gemm<false, false, false><<<gb, 256>>>(x, Wc, nullptr, nullptr, p_h, n);

    // 3. agg init with self-loop contribution
    int sl_threads = n * (CH / 4);
    k_selfloop<<<(sl_threads + 255) / 256, 256>>>(n);

    // 4. edge scatter (one warp per edge, grid-stride)
    k_scatter<<<2960, 256>>>(src, dst, ew, E);

    // 5. h2 = relu(relu(agg + bc) @ Wf^T + bf)
    k_gemm<true, true, true><<<gb, 256>>>(p_agg, Wf, bc, bf, p_h2, n);

    // 6. out = h2 @ Wf2^T + bf2
    k_gemm<false, true, false><<<gb, 256>>>(p_h2, Wf2, nullptr, bf2, out, n);
}

// round 6
// speedup vs baseline: 1.2946x; 1.2946x over previous
#include <cuda_runtime.h>
#include <cstdint>

// Problem constants: N=100000, C=128, E=3200000
#define MAXN 100000
#define CH 128
#define MAXE 3200000
#define SCAN_CHUNK 1024

// Scratch (device globals -- no allocation allowed)
__device__ float g_deg[MAXN];
__device__ float g_dinv[MAXN];
__device__ int   g_cnt[MAXN];        // in-degree histogram (excl self-loop)
__device__ int   g_start[MAXN + 1];  // CSR row offsets (sorted-by-dst)
__device__ int   g_pos[MAXN];        // running fill cursor for bucket pass
__device__ int   g_bsum[SCAN_CHUNK]; // block sums for 2-level scan
__device__ int   g_esrc[MAXE];       // per-edge src, dst-sorted
__device__ float g_enrm[MAXE];       // per-edge norm, dst-sorted
__device__ float g_h[(size_t)MAXN * CH];    // x @ Wc^T
__device__ float g_agg[(size_t)MAXN * CH];  // aggregated messages
__device__ float g_h2[(size_t)MAXN * CH];   // hidden after fc

// ---------------------------------------------------------------------------
// init: deg = 1 (self-loop weight), cnt = 0
// ---------------------------------------------------------------------------
__global__ void k_init(int n) {
    int i = blockIdx.x * blockDim.x + threadIdx.x;
    if (i < n) { g_deg[i] = 1.0f; g_cnt[i] = 0; }
}

// degree accum + histogram in one pass
__global__ void k_hist(const int* __restrict__ dst,
                       const float* __restrict__ ew, int E) {
    int i = blockIdx.x * blockDim.x + threadIdx.x;
    if (i < E) {
        int d = dst[i];
        atomicAdd(&g_deg[d], ew[i]);
        atomicAdd(&g_cnt[d], 1);
    }
}

__global__ void k_dinv(int n) {
    int i = blockIdx.x * blockDim.x + threadIdx.x;
    if (i < n) {
        float d = g_deg[i];
        g_dinv[i] = (d > 0.0f) ? rsqrtf(d) : 0.0f;
    }
}

// ---------------------------------------------------------------------------
// 2-level exclusive scan of g_cnt -> g_start (counting sort offsets)
// ---------------------------------------------------------------------------
__global__ __launch_bounds__(SCAN_CHUNK) void k_scan1(int n) {
    __shared__ int s[SCAN_CHUNK];
    int i = blockIdx.x * SCAN_CHUNK + threadIdx.x;
    int v = (i < n) ? g_cnt[i] : 0;
    s[threadIdx.x] = v;
    __syncthreads();
#pragma unroll
    for (int off = 1; off < SCAN_CHUNK; off <<= 1) {
        int t = (threadIdx.x >= off) ? s[threadIdx.x - off] : 0;
        __syncthreads();
        s[threadIdx.x] += t;
        __syncthreads();
    }
    if (i < n) g_start[i] = s[threadIdx.x] - v;  // exclusive within block
    if (threadIdx.x == SCAN_CHUNK - 1) g_bsum[blockIdx.x] = s[SCAN_CHUNK - 1];
}

__global__ __launch_bounds__(SCAN_CHUNK) void k_scan2(int nblk) {
    __shared__ int s[SCAN_CHUNK];
    int v = (threadIdx.x < nblk) ? g_bsum[threadIdx.x] : 0;
    s[threadIdx.x] = v;
    __syncthreads();
#pragma unroll
    for (int off = 1; off < SCAN_CHUNK; off <<= 1) {
        int t = (threadIdx.x >= off) ? s[threadIdx.x - off] : 0;
        __syncthreads();
        s[threadIdx.x] += t;
        __syncthreads();
    }
    if (threadIdx.x < nblk) g_bsum[threadIdx.x] = s[threadIdx.x] - v;  // exclusive
}

__global__ void k_scan3(int n, int E) {
    int i = blockIdx.x * blockDim.x + threadIdx.x;
    if (i < n) {
        int st = g_start[i] + g_bsum[i / SCAN_CHUNK];
        g_start[i] = st;
        g_pos[i] = st;
    }
    if (i == 0) g_start[n] = E;
}

// ---------------------------------------------------------------------------
// bucket pass: scatter (src, norm) records into dst-sorted order
// ---------------------------------------------------------------------------
__global__ void k_bucket(const int* __restrict__ src,
                         const int* __restrict__ dst,
                         const float* __restrict__ ew, int E) {
    int i = blockIdx.x * blockDim.x + threadIdx.x;
    if (i < E) {
        int s = src[i];
        int d = dst[i];
        float nrm = g_dinv[s] * ew[i] * g_dinv[d];
        int p = atomicAdd(&g_pos[d], 1);
        g_esrc[p] = s;
        g_enrm[p] = nrm;
    }
}

// ---------------------------------------------------------------------------
// aggregation: one warp per node, register accumulation, single store.
// acc init = self-loop term h[i]*dinv[i]^2  (replaces separate selfloop pass)
// ---------------------------------------------------------------------------
__global__ __launch_bounds__(256) void k_agg(int n) {
    int lane = threadIdx.x & 31;
    int node = (blockIdx.x * blockDim.x + threadIdx.x) >> 5;
    if (node >= n) return;

    float di = g_dinv[node];
    float w2 = di * di;
    float4 acc = ((const float4*)(g_h + (size_t)node * CH))[lane];
    acc.x *= w2; acc.y *= w2; acc.z *= w2; acc.w *= w2;

    int beg = g_start[node];
    int end = g_start[node + 1];
    for (int e0 = beg; e0 < end; e0 += 32) {
        int m = end - e0;
        if (m > 32) m = 32;
        int   sv = 0;
        float nv = 0.0f;
        if (lane < m) { sv = g_esrc[e0 + lane]; nv = g_enrm[e0 + lane]; }
        for (int j = 0; j < m; j++) {
            int   sj = __shfl_sync(0xffffffffu, sv, j);
            float nj = __shfl_sync(0xffffffffu, nv, j);
            float4 v = ((const float4*)(g_h + (size_t)sj * CH))[lane];
            acc.x = fmaf(v.x, nj, acc.x);
            acc.y = fmaf(v.y, nj, acc.y);
            acc.z = fmaf(v.z, nj, acc.z);
            acc.w = fmaf(v.w, nj, acc.w);
        }
    }
    ((float4*)(g_agg + (size_t)node * CH))[lane] = acc;
}

// ---------------------------------------------------------------------------
// SGEMM: C[m][n] = g( f(A[m][k]) * W[n][k] + bout[n] )   (unchanged from R5)
// ---------------------------------------------------------------------------
#define SSTR 132

template <bool RELU_IN, bool HAS_BOUT, bool RELU_OUT>
__global__ __launch_bounds__(256) void k_gemm(
    const float* __restrict__ A, const float* __restrict__ W,
    const float* __restrict__ bin, const float* __restrict__ bout,
    float* __restrict__ C, int M)
{
    __shared__ float As[32][SSTR];
    __shared__ float Ws[32][SSTR];

    int tid = threadIdx.x;
    int row0 = blockIdx.x * 128;
    int tx = tid & 15;
    int ty = tid >> 4;

    float acc[8][8];
#pragma unroll
    for (int i = 0; i < 8; i++)
#pragma unroll
        for (int j = 0; j < 8; j++) acc[i][j] = 0.0f;

    int lr = tid >> 3;
    int lk = (tid & 7) * 4;

    for (int k0 = 0; k0 < CH; k0 += 32) {
#pragma unroll
        for (int i = 0; i < 4; i++) {
            int r = lr + 32 * i;
            int gr = row0 + r;
            float4 v = make_float4(0.f, 0.f, 0.f, 0.f);
            if (gr < M) v = *(const float4*)(A + (size_t)gr * CH + k0 + lk);
            if (RELU_IN) {
                v.x = fmaxf(v.x + bin[k0 + lk + 0], 0.f);
                v.y = fmaxf(v.y + bin[k0 + lk + 1], 0.f);
                v.z = fmaxf(v.z + bin[k0 + lk + 2], 0.f);
                v.w = fmaxf(v.w + bin[k0 + lk + 3], 0.f);
            }
            As[lk + 0][r] = v.x;
            As[lk + 1][r] = v.y;
            As[lk + 2][r] = v.z;
            As[lk + 3][r] = v.w;
        }
#pragma unroll
        for (int i = 0; i < 4; i++) {
            int nn = lr + 32 * i;
            float4 v = *(const float4*)(W + (size_t)nn * CH + k0 + lk);
            Ws[lk + 0][nn] = v.x;
            Ws[lk + 1][nn] = v.y;
            Ws[lk + 2][nn] = v.z;
            Ws[lk + 3][nn] = v.w;
        }
        __syncthreads();

#pragma unroll
        for (int k = 0; k < 32; k++) {
            float a[8], b[8];
            *(float4*)(a)     = *(const float4*)&As[k][ty * 4];
            *(float4*)(a + 4) = *(const float4*)&As[k][64 + ty * 4];
            *(float4*)(b)     = *(const float4*)&Ws[k][tx * 4];
            *(float4*)(b + 4) = *(const float4*)&Ws[k][64 + tx * 4];
#pragma unroll
            for (int i = 0; i < 8; i++)
#pragma unroll
                for (int j = 0; j < 8; j++)
                    acc[i][j] = fmaf(a[i], b[j], acc[i][j]);
        }
        __syncthreads();
    }

#pragma unroll
    for (int i = 0; i < 8; i++) {
        int r = (i < 4) ? (ty * 4 + i) : (64 + ty * 4 + (i - 4));
        int gr = row0 + r;
        if (gr >= M) continue;
#pragma unroll
        for (int jj = 0; jj < 2; jj++) {
            int nbase = (jj == 0) ? (tx * 4) : (64 + tx * 4);
            float4 o;
            o.x = acc[i][jj * 4 + 0];
            o.y = acc[i][jj * 4 + 1];
            o.z = acc[i][jj * 4 + 2];
            o.w = acc[i][jj * 4 + 3];
            if (HAS_BOUT) {
                o.x += bout[nbase + 0];
                o.y += bout[nbase + 1];
                o.z += bout[nbase + 2];
                o.w += bout[nbase + 3];
            }
            if (RELU_OUT) {
                o.x = fmaxf(o.x, 0.f);
                o.y = fmaxf(o.y, 0.f);
                o.z = fmaxf(o.z, 0.f);
                o.w = fmaxf(o.w, 0.f);
            }
            *(float4*)(C + (size_t)gr * CH + nbase) = o;
        }
    }
}

// ---------------------------------------------------------------------------
// launch
// ---------------------------------------------------------------------------
extern "C" void kernel_launch(void* const* d_in, const int* in_sizes, int n_in,
                              void* d_out, int out_size) {
    const float* x   = (const float*)d_in[0];
    const int*   ei  = (const int*)d_in[1];    // int32 (JAX x64 disabled)
    const float* ew  = (const float*)d_in[2];
    const float* Wc  = (const float*)d_in[3];
    const float* bc  = (const float*)d_in[4];
    const float* Wf  = (const float*)d_in[5];
    const float* bf  = (const float*)d_in[6];
    const float* Wf2 = (const float*)d_in[7];
    const float* bf2 = (const float*)d_in[8];
    float*       out = (float*)d_out;

    int n = in_sizes[0] / CH;
    int E = in_sizes[2];
    const int* src = ei;
    const int* dst = ei + E;

    float *p_h, *p_agg, *p_h2;
    cudaGetSymbolAddress((void**)&p_h, g_h);
    cudaGetSymbolAddress((void**)&p_agg, g_agg);
    cudaGetSymbolAddress((void**)&p_h2, g_h2);

    int nblk = (n + SCAN_CHUNK - 1) / SCAN_CHUNK;

    // 1. degree + histogram, dinv
    k_init<<<(n + 255) / 256, 256>>>(n);
    k_hist<<<(E + 255) / 256, 256>>>(dst, ew, E);
    k_dinv<<<(n + 255) / 256, 256>>>(n);

    // 2. exclusive scan -> CSR offsets
    k_scan1<<<nblk, SCAN_CHUNK>>>(n);
    k_scan2<<<1, SCAN_CHUNK>>>(nblk);
    k_scan3<<<(n + 255) / 256, 256>>>(n, E);

    // 3. h = x @ Wc^T  (independent of sort; overlaps nothing but keeps order)
    int gb = (n + 127) / 128;
    k_gemm<false, false, false><<<gb, 256>>>(x, Wc, nullptr, nullptr, p_h, n);

    // 4. bucket edges by dst (counting sort payload pass)
    k_bucket<<<(E + 255) / 256, 256>>>(src, dst, ew, E);

    // 5. gather-only aggregation (self-loop folded into init)
    k_agg<<<(n * 32 + 255) / 256, 256>>>(n);

    // 6. h2 = relu(relu(agg + bc) @ Wf^T + bf)
    k_gemm<true, true, true><<<gb, 256>>>(p_agg, Wf, bc, bf, p_h2, n);

    // 7. out = h2 @ Wf2^T + bf2
    k_gemm<false, true, false><<<gb, 256>>>(p_h2, Wf2, nullptr, bf2, out, n);
}

// round 16
// speedup vs baseline: 1.4360x; 1.1092x over previous
#include <cuda_runtime.h>
#include <cuda_bf16.h>
#include <cstdint>

// Problem constants: N=100000, C=128, E=3200000
#define MAXN 100000
#define CH 128
#define MAXE 3200000
#define SCAN_CHUNK 1024

// Scratch (device globals -- no allocation allowed)
__device__ float g_deg[MAXN];
__device__ float g_dinv[MAXN];
__device__ int   g_cnt[MAXN];
__device__ int   g_start[MAXN + 1];
__device__ int   g_pos[MAXN];
__device__ int   g_bsum[SCAN_CHUNK];
__device__ int   g_esrc[MAXE];
__device__ float g_enrm[MAXE];
__device__ float g_h[(size_t)MAXN * CH];
__device__ float g_agg[(size_t)MAXN * CH];
__device__ float g_h2[(size_t)MAXN * CH];

// ---------------------------------------------------------------------------
// bf16 mma.sync GEMM (base PTX, no tcgen05 -- sm_103 ptxas-safe)
// C[m][n] = g( f(A[m][k]) * W[n][k] + bout[n] ),  3xBF16 split for accuracy.
// One CTA: 128x128 tile, K=128 fully staged in smem. 8 warps, 32x64 per warp.
// ---------------------------------------------------------------------------
#define SROW 68                      // u32 stride per row (136 bf16, pad)
#define A_HI 0
#define A_LO (128 * SROW)
#define W_HI (2 * 128 * SROW)
#define W_LO (3 * 128 * SROW)
#define GEMM_SMEM (4 * 128 * SROW * 4)   // 139264 bytes

__device__ __forceinline__ void mma_bf16(float& c0, float& c1, float& c2, float& c3,
                                         uint32_t a0, uint32_t a1, uint32_t a2, uint32_t a3,
                                         uint32_t b0, uint32_t b1) {
    asm volatile(
        "mma.sync.aligned.m16n8k16.row.col.f32.bf16.bf16.f32 "
        "{%0,%1,%2,%3}, {%4,%5,%6,%7}, {%8,%9}, {%0,%1,%2,%3};"
        : "+f"(c0), "+f"(c1), "+f"(c2), "+f"(c3)
        : "r"(a0), "r"(a1), "r"(a2), "r"(a3), "r"(b0), "r"(b1));
}

// split two floats into packed bf16x2 hi + lo residual
__device__ __forceinline__ void split2(float v0, float v1, uint32_t& hi, uint32_t& lo) {
    __nv_bfloat162 h = __floats2bfloat162_rn(v0, v1);   // x=v0(low), y=v1(high)
    float h0 = __bfloat162float(h.x);
    float h1 = __bfloat162float(h.y);
    __nv_bfloat162 l = __floats2bfloat162_rn(v0 - h0, v1 - h1);
    hi = *(uint32_t*)&h;
    lo = *(uint32_t*)&l;
}

template <bool RELU_IN, bool HAS_BOUT, bool RELU_OUT>
__global__ __launch_bounds__(256) void k_gemm_mma(
    const float* __restrict__ A, const float* __restrict__ W,
    const float* __restrict__ bin, const float* __restrict__ bout,
    float* __restrict__ C, int M)
{
    extern __shared__ uint32_t sm[];
    int tid = threadIdx.x;
    int row0 = blockIdx.x * 128;

    // ---- load + 3xBF16 split: A (128x128) and W (128x128) ----
    {
        int r = tid >> 1;               // 0..127
        int half = tid & 1;             // 0/1 -> cols 0..63 / 64..127
        int gr = row0 + r;
        const float* arow = A + (size_t)gr * CH;
        const float* wrow = W + (size_t)r * CH;
#pragma unroll
        for (int i = 0; i < 16; i++) {
            int col = half * 64 + i * 4;
            // A
            float4 v = make_float4(0.f, 0.f, 0.f, 0.f);
            if (gr < M) v = *(const float4*)(arow + col);
            if (RELU_IN) {
                float4 b = *(const float4*)(bin + col);
                v.x = fmaxf(v.x + b.x, 0.f);
                v.y = fmaxf(v.y + b.y, 0.f);
                v.z = fmaxf(v.z + b.z, 0.f);
                v.w = fmaxf(v.w + b.w, 0.f);
            }
            uint32_t h0, l0, h1, l1;
            split2(v.x, v.y, h0, l0);
            split2(v.z, v.w, h1, l1);
            int base = r * SROW + (col >> 1);
            sm[A_HI + base]     = h0;
            sm[A_HI + base + 1] = h1;
            sm[A_LO + base]     = l0;
            sm[A_LO + base + 1] = l1;
            // W
            float4 wv = *(const float4*)(wrow + col);
            split2(wv.x, wv.y, h0, l0);
            split2(wv.z, wv.w, h1, l1);
            sm[W_HI + base]     = h0;
            sm[W_HI + base + 1] = h1;
            sm[W_LO + base]     = l0;
            sm[W_LO + base + 1] = l1;
        }
    }
    __syncthreads();

    // ---- compute: warp w owns rows (w&3)*32..+31, cols (w>>2)*64..+63 ----
    int wid = tid >> 5;
    int lane = tid & 31;
    int tq = lane >> 2;   // 0..7
    int tr = lane & 3;    // 0..3
    int mrow0 = (wid & 3) * 32;
    int ncol0 = (wid >> 2) * 64;

    float acc[2][8][4];
#pragma unroll
    for (int mt = 0; mt < 2; mt++)
#pragma unroll
        for (int nt = 0; nt < 8; nt++)
#pragma unroll
            for (int j = 0; j < 4; j++) acc[mt][nt][j] = 0.0f;

#pragma unroll
    for (int ks = 0; ks < 8; ks++) {
        int kw = 8 * ks + tr;   // word offset within row
        uint32_t ah[2][4], al[2][4];
#pragma unroll
        for (int mt = 0; mt < 2; mt++) {
            int base = (mrow0 + mt * 16 + tq) * SROW + kw;
            ah[mt][0] = sm[A_HI + base];
            ah[mt][1] = sm[A_HI + base + 8 * SROW];
            ah[mt][2] = sm[A_HI + base + 4];
            ah[mt][3] = sm[A_HI + base + 8 * SROW + 4];
            al[mt][0] = sm[A_LO + base];
            al[mt][1] = sm[A_LO + base + 8 * SROW];
            al[mt][2] = sm[A_LO + base + 4];
            al[mt][3] = sm[A_LO + base + 8 * SROW + 4];
        }
        uint32_t bh[8][2], bl[8][2];
#pragma unroll
        for (int nt = 0; nt < 8; nt++) {
            int base = (ncol0 + nt * 8 + tq) * SROW + kw;
            bh[nt][0] = sm[W_HI + base];
            bh[nt][1] = sm[W_HI + base + 4];
            bl[nt][0] = sm[W_LO + base];
            bl[nt][1] = sm[W_LO + base + 4];
        }
#pragma unroll
        for (int mt = 0; mt < 2; mt++)
#pragma unroll
            for (int nt = 0; nt < 8; nt++) {
                mma_bf16(acc[mt][nt][0], acc[mt][nt][1], acc[mt][nt][2], acc[mt][nt][3],
                         ah[mt][0], ah[mt][1], ah[mt][2], ah[mt][3],
                         bh[nt][0], bh[nt][1]);
                mma_bf16(acc[mt][nt][0], acc[mt][nt][1], acc[mt][nt][2], acc[mt][nt][3],
                         ah[mt][0], ah[mt][1], ah[mt][2], ah[mt][3],
                         bl[nt][0], bl[nt][1]);
                mma_bf16(acc[mt][nt][0], acc[mt][nt][1], acc[mt][nt][2], acc[mt][nt][3],
                         al[mt][0], al[mt][1], al[mt][2], al[mt][3],
                         bh[nt][0], bh[nt][1]);
            }
    }

    // ---- epilogue: direct stores with fused bias / relu ----
#pragma unroll
    for (int mt = 0; mt < 2; mt++) {
        int row = mrow0 + mt * 16 + tq;
        int gr0 = row0 + row;
        int gr1 = gr0 + 8;
#pragma unroll
        for (int nt = 0; nt < 8; nt++) {
            int col = ncol0 + nt * 8 + 2 * tr;
            float2 b = make_float2(0.f, 0.f);
            if (HAS_BOUT) b = *(const float2*)(bout + col);
            float2 o0, o1;
            o0.x = acc[mt][nt][0] + b.x;
            o0.y = acc[mt][nt][1] + b.y;
            o1.x = acc[mt][nt][2] + b.x;
            o1.y = acc[mt][nt][3] + b.y;
            if (RELU_OUT) {
                o0.x = fmaxf(o0.x, 0.f); o0.y = fmaxf(o0.y, 0.f);
                o1.x = fmaxf(o1.x, 0.f); o1.y = fmaxf(o1.y, 0.f);
            }
            if (gr0 < M) *(float2*)(C + (size_t)gr0 * CH + col) = o0;
            if (gr1 < M) *(float2*)(C + (size_t)gr1 * CH + col) = o1;
        }
    }
}

// ---------------------------------------------------------------------------
// graph preprocessing (unchanged from R6, verified)
// ---------------------------------------------------------------------------
__global__ void k_init(int n) {
    int i = blockIdx.x * blockDim.x + threadIdx.x;
    if (i < n) { g_deg[i] = 1.0f; g_cnt[i] = 0; }
}

__global__ void k_hist(const int* __restrict__ dst,
                       const float* __restrict__ ew, int E) {
    int i = blockIdx.x * blockDim.x + threadIdx.x;
    if (i < E) {
        int d = dst[i];
        atomicAdd(&g_deg[d], ew[i]);
        atomicAdd(&g_cnt[d], 1);
    }
}

__global__ void k_dinv(int n) {
    int i = blockIdx.x * blockDim.x + threadIdx.x;
    if (i < n) {
        float d = g_deg[i];
        g_dinv[i] = (d > 0.0f) ? rsqrtf(d) : 0.0f;
    }
}

__global__ __launch_bounds__(SCAN_CHUNK) void k_scan1(int n) {
    __shared__ int s[SCAN_CHUNK];
    int i = blockIdx.x * SCAN_CHUNK + threadIdx.x;
    int v = (i < n) ? g_cnt[i] : 0;
    s[threadIdx.x] = v;
    __syncthreads();
#pragma unroll
    for (int off = 1; off < SCAN_CHUNK; off <<= 1) {
        int t = (threadIdx.x >= off) ? s[threadIdx.x - off] : 0;
        __syncthreads();
        s[threadIdx.x] += t;
        __syncthreads();
    }
    if (i < n) g_start[i] = s[threadIdx.x] - v;
    if (threadIdx.x == SCAN_CHUNK - 1) g_bsum[blockIdx.x] = s[SCAN_CHUNK - 1];
}

__global__ __launch_bounds__(SCAN_CHUNK) void k_scan2(int nblk) {
    __shared__ int s[SCAN_CHUNK];
    int v = (threadIdx.x < nblk) ? g_bsum[threadIdx.x] : 0;
    s[threadIdx.x] = v;
    __syncthreads();
#pragma unroll
    for (int off = 1; off < SCAN_CHUNK; off <<= 1) {
        int t = (threadIdx.x >= off) ? s[threadIdx.x - off] : 0;
        __syncthreads();
        s[threadIdx.x] += t;
        __syncthreads();
    }
    if (threadIdx.x < nblk) g_bsum[threadIdx.x] = s[threadIdx.x] - v;
}

__global__ void k_scan3(int n, int E) {
    int i = blockIdx.x * blockDim.x + threadIdx.x;
    if (i < n) {
        int st = g_start[i] + g_bsum[i / SCAN_CHUNK];
        g_start[i] = st;
        g_pos[i] = st;
    }
    if (i == 0) g_start[n] = E;
}

__global__ void k_bucket(const int* __restrict__ src,
                         const int* __restrict__ dst,
                         const float* __restrict__ ew, int E) {
    int i = blockIdx.x * blockDim.x + threadIdx.x;
    if (i < E) {
        int s = src[i];
        int d = dst[i];
        float nrm = g_dinv[s] * ew[i] * g_dinv[d];
        int p = atomicAdd(&g_pos[d], 1);
        g_esrc[p] = s;
        g_enrm[p] = nrm;
    }
}

__global__ __launch_bounds__(256) void k_agg(int n) {
    int lane = threadIdx.x & 31;
    int node = (blockIdx.x * blockDim.x + threadIdx.x) >> 5;
    if (node >= n) return;

    float di = g_dinv[node];
    float w2 = di * di;
    float4 acc = ((const float4*)(g_h + (size_t)node * CH))[lane];
    acc.x *= w2; acc.y *= w2; acc.z *= w2; acc.w *= w2;

    int beg = g_start[node];
    int end = g_start[node + 1];
    for (int e0 = beg; e0 < end; e0 += 32) {
        int m = end - e0;
        if (m > 32) m = 32;
        int   sv = 0;
        float nv = 0.0f;
        if (lane < m) { sv = g_esrc[e0 + lane]; nv = g_enrm[e0 + lane]; }
        for (int j = 0; j < m; j++) {
            int   sj = __shfl_sync(0xffffffffu, sv, j);
            float nj = __shfl_sync(0xffffffffu, nv, j);
            float4 v = ((const float4*)(g_h + (size_t)sj * CH))[lane];
            acc.x = fmaf(v.x, nj, acc.x);
            acc.y = fmaf(v.y, nj, acc.y);
            acc.z = fmaf(v.z, nj, acc.z);
            acc.w = fmaf(v.w, nj, acc.w);
        }
    }
    ((float4*)(g_agg + (size_t)node * CH))[lane] = acc;
}

// ---------------------------------------------------------------------------
// launch
// ---------------------------------------------------------------------------
extern "C" void kernel_launch(void* const* d_in, const int* in_sizes, int n_in,
                              void* d_out, int out_size) {
    const float* x   = (const float*)d_in[0];
    const int*   ei  = (const int*)d_in[1];    // int32 (JAX x64 disabled)
    const float* ew  = (const float*)d_in[2];
    const float* Wc  = (const float*)d_in[3];
    const float* bc  = (const float*)d_in[4];
    const float* Wf  = (const float*)d_in[5];
    const float* bf  = (const float*)d_in[6];
    const float* Wf2 = (const float*)d_in[7];
    const float* bf2 = (const float*)d_in[8];
    float*       out = (float*)d_out;

    int n = in_sizes[0] / CH;
    int E = in_sizes[2];
    const int* src = ei;
    const int* dst = ei + E;

    float *p_h, *p_agg, *p_h2;
    cudaGetSymbolAddress((void**)&p_h, g_h);
    cudaGetSymbolAddress((void**)&p_agg, g_agg);
    cudaGetSymbolAddress((void**)&p_h2, g_h2);

    static bool attr_done = false;
    if (!attr_done) {
        cudaFuncSetAttribute(k_gemm_mma<false, false, false>,
                             cudaFuncAttributeMaxDynamicSharedMemorySize, GEMM_SMEM);
        cudaFuncSetAttribute(k_gemm_mma<true, true, true>,
                             cudaFuncAttributeMaxDynamicSharedMemorySize, GEMM_SMEM);
        cudaFuncSetAttribute(k_gemm_mma<false, true, false>,
                             cudaFuncAttributeMaxDynamicSharedMemorySize, GEMM_SMEM);
        attr_done = true;
    }

    int nblk = (n + SCAN_CHUNK - 1) / SCAN_CHUNK;

    // 1. degree + histogram, dinv
    k_init<<<(n + 255) / 256, 256>>>(n);
    k_hist<<<(E + 255) / 256, 256>>>(dst, ew, E);
    k_dinv<<<(n + 255) / 256, 256>>>(n);

    // 2. exclusive scan -> CSR offsets
    k_scan1<<<nblk, SCAN_CHUNK>>>(n);
    k_scan2<<<1, SCAN_CHUNK>>>(nblk);
    k_scan3<<<(n + 255) / 256, 256>>>(n, E);

    // 3. h = x @ Wc^T   (3xBF16 mma.sync)
    int gb = (n + 127) / 128;
    k_gemm_mma<false, false, false><<<gb, 256, GEMM_SMEM>>>(x, Wc, nullptr, nullptr, p_h, n);

    // 4. bucket edges by dst
    k_bucket<<<(E + 255) / 256, 256>>>(src, dst, ew, E);

    // 5. gather-only aggregation
    k_agg<<<(n * 32 + 255) / 256, 256>>>(n);

    // 6. h2 = relu(relu(agg + bc) @ Wf^T + bf)
    k_gemm_mma<true, true, true><<<gb, 256, GEMM_SMEM>>>(p_agg, Wf, bc, bf, p_h2, n);

    // 7. out = h2 @ Wf2^T + bf2
    k_gemm_mma<false, true, false><<<gb, 256, GEMM_SMEM>>>(p_h2, Wf2, nullptr, bf2, out, n);
}